// round 7
// baseline (speedup 1.0000x reference)
#include <cuda_runtime.h>

#define NSIDE    48
#define NPIX     2304          // 48*48
#define LDW      52            // padded smem row stride (floats)
#define NTHREADS 288           // 24 row-groups(2 rows) x 12 col-groups(4 cols)
#define NWARPS   9
#define INV_EPS  100.0f
#define MAXB     64

__device__ float g_cost[MAXB];
__device__ unsigned int g_count = 0;

typedef unsigned long long u64t;

__device__ __forceinline__ float4 ld4(const float* p) {
    return *reinterpret_cast<const float4*>(p);
}
__device__ __forceinline__ void st4(float* p, float4 v) {
    *reinterpret_cast<float4*>(p) = v;
}
__device__ __forceinline__ float mass_of(float x) {
    return fminf(fmaxf(x, 0.0f), 1e9f) + 1e-9f;
}

// ---- packed f32x2 helpers (FFMA2: 2 MACs per instruction per lane) --------
__device__ __forceinline__ u64t pack2(float v) {
    u64t r; asm("mov.b64 %0, {%1, %1};" : "=l"(r) : "f"(v)); return r;
}
__device__ __forceinline__ u64t ffma2(u64t a, u64t b, u64t c) {
    u64t d; asm("fma.rn.f32x2 %0, %1, %2, %3;" : "=l"(d) : "l"(a), "l"(b), "l"(c));
    return d;
}
__device__ __forceinline__ float2 unpack2(u64t v) {
    float2 f; asm("mov.b64 {%0, %1}, %2;" : "=f"(f.x), "=f"(f.y) : "l"(v));
    return f;
}

// ---------------------------------------------------------------------------
// block reduce (all threads receive the sum; deterministic order)
// ---------------------------------------------------------------------------
__device__ __forceinline__ float block_reduce(float val, float* red) {
#pragma unroll
    for (int o = 16; o; o >>= 1) val += __shfl_down_sync(0xffffffffu, val, o);
    if ((threadIdx.x & 31) == 0) red[threadIdx.x >> 5] = val;
    __syncthreads();
    float s = red[0];
#pragma unroll
    for (int w = 1; w < NWARPS; w++) s += red[w];
    __syncthreads();
    return s;
}

// ---------------------------------------------------------------------------
// Dense 48x48 matmul slice with packed math:
//   acc[i][j] (f32x2) = (A*B)[r0+i, c0 + 2j .. c0+2j+1]
// A rows loaded as float4 every 4 k-iters (LDS.128); B as ulonglong2 (LDS.128).
// ---------------------------------------------------------------------------
__device__ __forceinline__ void mm2x4_f2(const float* __restrict__ A,
                                         const float* __restrict__ B,
                                         int r0, int c0, u64t acc[2][2]) {
    acc[0][0] = acc[0][1] = acc[1][0] = acc[1][1] = 0ull;   // (0.f,0.f)
    const float* a0p = A + r0 * LDW;
    const float* a1p = a0p + LDW;
#pragma unroll 3
    for (int b4 = 0; b4 < NSIDE; b4 += 4) {
        float4 av0 = ld4(a0p + b4);
        float4 av1 = ld4(a1p + b4);
        const float* bp = B + b4 * LDW + c0;
#pragma unroll
        for (int k = 0; k < 4; k++) {
            float a0s = (k == 0) ? av0.x : (k == 1) ? av0.y : (k == 2) ? av0.z : av0.w;
            float a1s = (k == 0) ? av1.x : (k == 1) ? av1.y : (k == 2) ? av1.z : av1.w;
            u64t a0 = pack2(a0s);
            u64t a1 = pack2(a1s);
            ulonglong2 bv = *reinterpret_cast<const ulonglong2*>(bp + k * LDW);
            acc[0][0] = ffma2(a0, bv.x, acc[0][0]);
            acc[0][1] = ffma2(a0, bv.y, acc[0][1]);
            acc[1][0] = ffma2(a1, bv.x, acc[1][0]);
            acc[1][1] = ffma2(a1, bv.y, acc[1][1]);
        }
    }
}

__device__ __forceinline__ void st_acc(float* dst, u64t acc0, u64t acc1) {
    ulonglong2 v; v.x = acc0; v.y = acc1;
    *reinterpret_cast<ulonglong2*>(dst) = v;
}

// ---------------------------------------------------------------------------
// One CTA per batch image. Sinkhorn in the multiplicative (scaling) domain:
//   a = e^{u/eps}, b = e^{v/eps};  a <- mu*a/(a*(K b K) + 1e-6), etc.
// Algebraically identical to the reference log-domain update (+1e-6 lse).
// ---------------------------------------------------------------------------
__global__ __launch_bounds__(NTHREADS)
void sinkhorn_kernel(const float* __restrict__ y, const float* __restrict__ yt,
                     float* __restrict__ out, int nb) {
    __shared__ __align__(16) float sK[NSIDE * LDW];
    __shared__ __align__(16) float sA[NSIDE * LDW];
    __shared__ __align__(16) float sB[NSIDE * LDW];
    __shared__ __align__(16) float sT[NSIDE * LDW];
    __shared__ float ktab[NSIDE];
    __shared__ float kdtab[NSIDE];
    __shared__ float red[NWARPS];

    const int tid = threadIdx.x;
    const int r0  = (tid / 12) * 2;
    const int c0  = (tid % 12) * 4;

    const float* yb  = y  + (size_t)blockIdx.x * NPIX;
    const float* ytb = yt + (size_t)blockIdx.x * NPIX;

    if (tid < NSIDE) {
        float dd = (float)tid * (1.0f / 48.0f);
        float d2 = dd * dd;
        float k  = expf(-d2 * INV_EPS);
        ktab[tid]  = k;
        kdtab[tid] = k * d2;
    }
    for (int i = tid; i < NPIX; i += NTHREADS) {
        int ro = i / NSIDE, co = i % NSIDE;
        int d  = ro - co; d = d < 0 ? -d : d;
        float dd = (float)d * (1.0f / 48.0f);
        sK[ro * LDW + co] = expf(-dd * dd * INV_EPS);
    }

    float sxl = 0.0f, syl = 0.0f;
    for (int i = tid; i < NPIX; i += NTHREADS) {
        sxl += mass_of(yb[i]);
        syl += mass_of(ytb[i]);
    }
    __syncthreads();
    const float sx = block_reduce(sxl, red);
    const float sy = block_reduce(syl, red);
    const float rsx = 1.0f / sx, rsy = 1.0f / sy;

    float4 mu4[2], nu4[2], a4[2], b4[2];
#pragma unroll
    for (int i = 0; i < 2; i++) {
        int gidx = (r0 + i) * NSIDE + c0;
        float4 yv  = ld4(yb  + gidx);
        float4 ytv = ld4(ytb + gidx);
        mu4[i] = make_float4(mass_of(yv.x) * rsx, mass_of(yv.y) * rsx,
                             mass_of(yv.z) * rsx, mass_of(yv.w) * rsx);
        nu4[i] = make_float4(mass_of(ytv.x) * rsy, mass_of(ytv.y) * rsy,
                             mass_of(ytv.z) * rsy, mass_of(ytv.w) * rsy);
        a4[i] = make_float4(1.f, 1.f, 1.f, 1.f);
        b4[i] = make_float4(1.f, 1.f, 1.f, 1.f);
        st4(&sA[(r0 + i) * LDW + c0], a4[i]);
        st4(&sB[(r0 + i) * LDW + c0], b4[i]);
    }
    __syncthreads();

    u64t t[2][2], s[2][2];
#pragma unroll 1
    for (int it = 0; it < 5; it++) {
        // u-update: S = K*B*K ; a <- mu*a / (a*S + 1e-6)
        mm2x4_f2(sK, sB, r0, c0, t);
        st_acc(&sT[r0 * LDW + c0], t[0][0], t[0][1]);
        st_acc(&sT[(r0 + 1) * LDW + c0], t[1][0], t[1][1]);
        __syncthreads();
        mm2x4_f2(sT, sK, r0, c0, s);
#pragma unroll
        for (int i = 0; i < 2; i++) {
            float2 slo = unpack2(s[i][0]);
            float2 shi = unpack2(s[i][1]);
            a4[i].x = __fdividef(mu4[i].x * a4[i].x, fmaf(a4[i].x, slo.x, 1e-6f));
            a4[i].y = __fdividef(mu4[i].y * a4[i].y, fmaf(a4[i].y, slo.y, 1e-6f));
            a4[i].z = __fdividef(mu4[i].z * a4[i].z, fmaf(a4[i].z, shi.x, 1e-6f));
            a4[i].w = __fdividef(mu4[i].w * a4[i].w, fmaf(a4[i].w, shi.y, 1e-6f));
            st4(&sA[(r0 + i) * LDW + c0], a4[i]);
        }
        __syncthreads();

        // v-update: S = K*A*K ; b <- nu*b / (b*S + 1e-6)
        mm2x4_f2(sK, sA, r0, c0, t);
        st_acc(&sT[r0 * LDW + c0], t[0][0], t[0][1]);
        st_acc(&sT[(r0 + 1) * LDW + c0], t[1][0], t[1][1]);
        __syncthreads();
        mm2x4_f2(sT, sK, r0, c0, s);
#pragma unroll
        for (int i = 0; i < 2; i++) {
            float2 slo = unpack2(s[i][0]);
            float2 shi = unpack2(s[i][1]);
            b4[i].x = __fdividef(nu4[i].x * b4[i].x, fmaf(b4[i].x, slo.x, 1e-6f));
            b4[i].y = __fdividef(nu4[i].y * b4[i].y, fmaf(b4[i].y, slo.y, 1e-6f));
            b4[i].z = __fdividef(nu4[i].z * b4[i].z, fmaf(b4[i].z, shi.x, 1e-6f));
            b4[i].w = __fdividef(nu4[i].w * b4[i].w, fmaf(b4[i].w, shi.y, 1e-6f));
            st4(&sB[(r0 + i) * LDW + c0], b4[i]);
        }
        __syncthreads();
    }

    // cost = sum_i a_i * [ (KD*B*K) + (K*B*KD) ]_i  — 2 fused passes.
    // Pass 1: T1 = KD*B (-> sT), T2 = K*B (-> sA; a lives in registers).
    {
        float4 t1[2], t2[2];
        t1[0] = t1[1] = t2[0] = t2[1] = make_float4(0.f, 0.f, 0.f, 0.f);
#pragma unroll 8
        for (int b = 0; b < NSIDE; b++) {
            int d0 = r0 - b;     d0 = d0 < 0 ? -d0 : d0;
            int d1 = r0 + 1 - b; d1 = d1 < 0 ? -d1 : d1;
            float kd0 = kdtab[d0], kd1 = kdtab[d1];
            float k0  = ktab[d0],  k1  = ktab[d1];
            float4 bv = ld4(sB + b * LDW + c0);
            t1[0].x = fmaf(kd0, bv.x, t1[0].x); t1[0].y = fmaf(kd0, bv.y, t1[0].y);
            t1[0].z = fmaf(kd0, bv.z, t1[0].z); t1[0].w = fmaf(kd0, bv.w, t1[0].w);
            t1[1].x = fmaf(kd1, bv.x, t1[1].x); t1[1].y = fmaf(kd1, bv.y, t1[1].y);
            t1[1].z = fmaf(kd1, bv.z, t1[1].z); t1[1].w = fmaf(kd1, bv.w, t1[1].w);
            t2[0].x = fmaf(k0, bv.x, t2[0].x);  t2[0].y = fmaf(k0, bv.y, t2[0].y);
            t2[0].z = fmaf(k0, bv.z, t2[0].z);  t2[0].w = fmaf(k0, bv.w, t2[0].w);
            t2[1].x = fmaf(k1, bv.x, t2[1].x);  t2[1].y = fmaf(k1, bv.y, t2[1].y);
            t2[1].z = fmaf(k1, bv.z, t2[1].z);  t2[1].w = fmaf(k1, bv.w, t2[1].w);
        }
        __syncthreads();
        st4(&sT[r0 * LDW + c0], t1[0]);
        st4(&sT[(r0 + 1) * LDW + c0], t1[1]);
        st4(&sA[r0 * LDW + c0], t2[0]);
        st4(&sA[(r0 + 1) * LDW + c0], t2[1]);
        __syncthreads();
    }

    // Pass 2: S1 = T1*K, S2 = T2*KD; cl = sum a .* (S1 + S2)
    float cl = 0.0f;
    {
        float4 s1[2], s2[2];
        s1[0] = s1[1] = s2[0] = s2[1] = make_float4(0.f, 0.f, 0.f, 0.f);
        const float* t1p0 = sT + r0 * LDW;
        const float* t1p1 = sT + (r0 + 1) * LDW;
        const float* t2p0 = sA + r0 * LDW;
        const float* t2p1 = sA + (r0 + 1) * LDW;
#pragma unroll 8
        for (int b = 0; b < NSIDE; b++) {
            float p0 = t1p0[b], p1 = t1p1[b];
            float q0 = t2p0[b], q1 = t2p1[b];
            float4 kv = ld4(sK + b * LDW + c0);
            int e0 = b - c0;     e0 = e0 < 0 ? -e0 : e0;
            int e1 = b - c0 - 1; e1 = e1 < 0 ? -e1 : e1;
            int e2 = b - c0 - 2; e2 = e2 < 0 ? -e2 : e2;
            int e3 = b - c0 - 3; e3 = e3 < 0 ? -e3 : e3;
            float kd0 = kdtab[e0], kd1 = kdtab[e1], kd2 = kdtab[e2], kd3 = kdtab[e3];
            s1[0].x = fmaf(p0, kv.x, s1[0].x); s1[0].y = fmaf(p0, kv.y, s1[0].y);
            s1[0].z = fmaf(p0, kv.z, s1[0].z); s1[0].w = fmaf(p0, kv.w, s1[0].w);
            s1[1].x = fmaf(p1, kv.x, s1[1].x); s1[1].y = fmaf(p1, kv.y, s1[1].y);
            s1[1].z = fmaf(p1, kv.z, s1[1].z); s1[1].w = fmaf(p1, kv.w, s1[1].w);
            s2[0].x = fmaf(q0, kd0, s2[0].x);  s2[0].y = fmaf(q0, kd1, s2[0].y);
            s2[0].z = fmaf(q0, kd2, s2[0].z);  s2[0].w = fmaf(q0, kd3, s2[0].w);
            s2[1].x = fmaf(q1, kd0, s2[1].x);  s2[1].y = fmaf(q1, kd1, s2[1].y);
            s2[1].z = fmaf(q1, kd2, s2[1].z);  s2[1].w = fmaf(q1, kd3, s2[1].w);
        }
#pragma unroll
        for (int i = 0; i < 2; i++) {
            cl += a4[i].x * (s1[i].x + s2[i].x);
            cl += a4[i].y * (s1[i].y + s2[i].y);
            cl += a4[i].z * (s1[i].z + s2[i].z);
            cl += a4[i].w * (s1[i].w + s2[i].w);
        }
    }

    float c = block_reduce(cl, red);

    // last CTA finalizes the batch mean (counter self-resets: replay-safe)
    if (tid == 0) {
        g_cost[blockIdx.x] = c;
        __threadfence();
        unsigned done = atomicAdd(&g_count, 1u);
        if (done == (unsigned)(nb - 1)) {
            float ssum = 0.0f;
            for (int i = 0; i < nb; i++) ssum += g_cost[i];
            *out = ssum / (float)nb;
            g_count = 0;
        }
    }
}

extern "C" void kernel_launch(void* const* d_in, const int* in_sizes, int n_in,
                              void* d_out, int out_size) {
    const float* y  = (const float*)d_in[0];
    const float* yt = (const float*)d_in[1];
    float* out = (float*)d_out;

    int nb = in_sizes[0] / NPIX;   // 16
    if (nb < 1)    nb = 1;
    if (nb > MAXB) nb = MAXB;

    sinkhorn_kernel<<<nb, NTHREADS>>>(y, yt, out, nb);
}

// round 8
// speedup vs baseline: 1.1039x; 1.1039x over previous
#include <cuda_runtime.h>

#define NSIDE    48
#define NPIX     2304          // 48*48
#define LDW      52            // padded smem row stride (floats)
#define NTHREADS 288           // 9 warps: 3x3 grid of 16x16 warp tiles
#define NWARPS   9
#define INV_EPS  100.0f
#define MAXB     64

__device__ float g_cost[MAXB];
__device__ unsigned int g_count = 0;

typedef unsigned long long u64t;

__device__ __forceinline__ float4 ld4(const float* p) {
    return *reinterpret_cast<const float4*>(p);
}
__device__ __forceinline__ void st4(float* p, float4 v) {
    *reinterpret_cast<float4*>(p) = v;
}
__device__ __forceinline__ float mass_of(float x) {
    return fminf(fmaxf(x, 0.0f), 1e9f) + 1e-9f;
}

// ---- packed f32x2 helpers --------------------------------------------------
__device__ __forceinline__ u64t pack2(float v) {
    u64t r; asm("mov.b64 %0, {%1, %1};" : "=l"(r) : "f"(v)); return r;
}
__device__ __forceinline__ u64t ffma2(u64t a, u64t b, u64t c) {
    u64t d; asm("fma.rn.f32x2 %0, %1, %2, %3;" : "=l"(d) : "l"(a), "l"(b), "l"(c));
    return d;
}
__device__ __forceinline__ float2 unpack2(u64t v) {
    float2 f; asm("mov.b64 {%0, %1}, %2;" : "=f"(f.x), "=f"(f.y) : "l"(v));
    return f;
}

// ---------------------------------------------------------------------------
// block reduce (all threads receive the sum; deterministic order)
// ---------------------------------------------------------------------------
__device__ __forceinline__ float block_reduce(float val, float* red) {
#pragma unroll
    for (int o = 16; o; o >>= 1) val += __shfl_down_sync(0xffffffffu, val, o);
    if ((threadIdx.x & 31) == 0) red[threadIdx.x >> 5] = val;
    __syncthreads();
    float s = red[0];
#pragma unroll
    for (int w = 1; w < NWARPS; w++) s += red[w];
    __syncthreads();
    return s;
}

// ---------------------------------------------------------------------------
// Dense 48x48 matmul slice with warp-blocked 16x16 tiles:
//   thread computes rows {rA, rB}=(rA+8) x cols c0..c0+3.
//   B load: 64B/warp/iter (broadcast-dedup across 8 row slots) -> 1 wavefront.
//   A load: LDS.128 per row per 4 iters, banks 20*lr mod 32 all distinct.
// ---------------------------------------------------------------------------
__device__ __forceinline__ void mm_wb(const float* __restrict__ A,
                                      const float* __restrict__ B,
                                      int rA, int rB, int c0, u64t acc[2][2]) {
    acc[0][0] = acc[0][1] = acc[1][0] = acc[1][1] = 0ull;
    const float* a0p = A + rA * LDW;
    const float* a1p = A + rB * LDW;
#pragma unroll 4
    for (int b4 = 0; b4 < NSIDE; b4 += 4) {
        float4 av0 = ld4(a0p + b4);
        float4 av1 = ld4(a1p + b4);
        const float* bp = B + b4 * LDW + c0;
#pragma unroll
        for (int k = 0; k < 4; k++) {
            float a0s = (k == 0) ? av0.x : (k == 1) ? av0.y : (k == 2) ? av0.z : av0.w;
            float a1s = (k == 0) ? av1.x : (k == 1) ? av1.y : (k == 2) ? av1.z : av1.w;
            u64t a0 = pack2(a0s);
            u64t a1 = pack2(a1s);
            ulonglong2 bv = *reinterpret_cast<const ulonglong2*>(bp + k * LDW);
            acc[0][0] = ffma2(a0, bv.x, acc[0][0]);
            acc[0][1] = ffma2(a0, bv.y, acc[0][1]);
            acc[1][0] = ffma2(a1, bv.x, acc[1][0]);
            acc[1][1] = ffma2(a1, bv.y, acc[1][1]);
        }
    }
}

__device__ __forceinline__ void st_acc(float* dst, u64t acc0, u64t acc1) {
    ulonglong2 v; v.x = acc0; v.y = acc1;
    *reinterpret_cast<ulonglong2*>(dst) = v;
}

// ---------------------------------------------------------------------------
// One CTA per batch image. Sinkhorn in the multiplicative (scaling) domain:
//   a = e^{u/eps}, b = e^{v/eps};  a <- mu*a/(a*(K b K) + 1e-6), etc.
// Algebraically identical to the reference log-domain update (+1e-6 lse).
// ---------------------------------------------------------------------------
__global__ __launch_bounds__(NTHREADS)
void sinkhorn_kernel(const float* __restrict__ y, const float* __restrict__ yt,
                     float* __restrict__ out, int nb) {
    __shared__ __align__(16) float sK[NSIDE * LDW];
    __shared__ __align__(16) float sA[NSIDE * LDW];
    __shared__ __align__(16) float sB[NSIDE * LDW];
    __shared__ __align__(16) float sT[NSIDE * LDW];
    __shared__ float ktab[NSIDE];
    __shared__ float kdtab[NSIDE];
    __shared__ float red[NWARPS];

    const int tid  = threadIdx.x;
    const int wid  = tid >> 5;
    const int lane = tid & 31;
    const int wr   = wid / 3;            // warp row-block 0..2
    const int wc   = wid % 3;            // warp col-block 0..2
    const int lr   = lane >> 2;          // row slot 0..7
    const int lc   = lane & 3;           // col slot 0..3
    const int rA   = wr * 16 + lr;       // first row
    const int rB   = rA + 8;             // second row
    const int c0   = wc * 16 + lc * 4;   // col block

    const float* yb  = y  + (size_t)blockIdx.x * NPIX;
    const float* ytb = yt + (size_t)blockIdx.x * NPIX;

    if (tid < NSIDE) {
        float dd = (float)tid * (1.0f / 48.0f);
        float d2 = dd * dd;
        float k  = expf(-d2 * INV_EPS);
        ktab[tid]  = k;
        kdtab[tid] = k * d2;
    }
    for (int i = tid; i < NPIX; i += NTHREADS) {
        int ro = i / NSIDE, co = i % NSIDE;
        int d  = ro - co; d = d < 0 ? -d : d;
        float dd = (float)d * (1.0f / 48.0f);
        sK[ro * LDW + co] = expf(-dd * dd * INV_EPS);
    }

    float sxl = 0.0f, syl = 0.0f;
    for (int i = tid; i < NPIX; i += NTHREADS) {
        sxl += mass_of(yb[i]);
        syl += mass_of(ytb[i]);
    }
    __syncthreads();
    const float sx = block_reduce(sxl, red);
    const float sy = block_reduce(syl, red);
    const float rsx = 1.0f / sx, rsy = 1.0f / sy;

    float4 mu4[2], nu4[2], a4[2], b4[2];
    const int rows[2] = {rA, rB};
#pragma unroll
    for (int i = 0; i < 2; i++) {
        int gidx = rows[i] * NSIDE + c0;
        float4 yv  = ld4(yb  + gidx);
        float4 ytv = ld4(ytb + gidx);
        mu4[i] = make_float4(mass_of(yv.x) * rsx, mass_of(yv.y) * rsx,
                             mass_of(yv.z) * rsx, mass_of(yv.w) * rsx);
        nu4[i] = make_float4(mass_of(ytv.x) * rsy, mass_of(ytv.y) * rsy,
                             mass_of(ytv.z) * rsy, mass_of(ytv.w) * rsy);
        a4[i] = make_float4(1.f, 1.f, 1.f, 1.f);
        b4[i] = make_float4(1.f, 1.f, 1.f, 1.f);
        st4(&sA[rows[i] * LDW + c0], a4[i]);
        st4(&sB[rows[i] * LDW + c0], b4[i]);
    }
    __syncthreads();

    u64t t[2][2], s[2][2];
#pragma unroll 1
    for (int it = 0; it < 5; it++) {
        // u-update: S = K*B*K ; a <- mu*a / (a*S + 1e-6)
        mm_wb(sK, sB, rA, rB, c0, t);
        st_acc(&sT[rA * LDW + c0], t[0][0], t[0][1]);
        st_acc(&sT[rB * LDW + c0], t[1][0], t[1][1]);
        __syncthreads();
        mm_wb(sT, sK, rA, rB, c0, s);
#pragma unroll
        for (int i = 0; i < 2; i++) {
            float2 slo = unpack2(s[i][0]);
            float2 shi = unpack2(s[i][1]);
            a4[i].x = __fdividef(mu4[i].x * a4[i].x, fmaf(a4[i].x, slo.x, 1e-6f));
            a4[i].y = __fdividef(mu4[i].y * a4[i].y, fmaf(a4[i].y, slo.y, 1e-6f));
            a4[i].z = __fdividef(mu4[i].z * a4[i].z, fmaf(a4[i].z, shi.x, 1e-6f));
            a4[i].w = __fdividef(mu4[i].w * a4[i].w, fmaf(a4[i].w, shi.y, 1e-6f));
            st4(&sA[rows[i] * LDW + c0], a4[i]);
        }
        __syncthreads();

        // v-update: S = K*A*K ; b <- nu*b / (b*S + 1e-6)
        mm_wb(sK, sA, rA, rB, c0, t);
        st_acc(&sT[rA * LDW + c0], t[0][0], t[0][1]);
        st_acc(&sT[rB * LDW + c0], t[1][0], t[1][1]);
        __syncthreads();
        mm_wb(sT, sK, rA, rB, c0, s);
#pragma unroll
        for (int i = 0; i < 2; i++) {
            float2 slo = unpack2(s[i][0]);
            float2 shi = unpack2(s[i][1]);
            b4[i].x = __fdividef(nu4[i].x * b4[i].x, fmaf(b4[i].x, slo.x, 1e-6f));
            b4[i].y = __fdividef(nu4[i].y * b4[i].y, fmaf(b4[i].y, slo.y, 1e-6f));
            b4[i].z = __fdividef(nu4[i].z * b4[i].z, fmaf(b4[i].z, shi.x, 1e-6f));
            b4[i].w = __fdividef(nu4[i].w * b4[i].w, fmaf(b4[i].w, shi.y, 1e-6f));
            st4(&sB[rows[i] * LDW + c0], b4[i]);
        }
        __syncthreads();
    }

    // cost = sum_i a_i * [ (KD*B*K) + (K*B*KD) ]_i  — 2 fused passes.
    // Pass 1: T1 = KD*B (-> sT), T2 = K*B (-> sA; a lives in registers).
    {
        float4 t1[2], t2[2];
        t1[0] = t1[1] = t2[0] = t2[1] = make_float4(0.f, 0.f, 0.f, 0.f);
#pragma unroll 8
        for (int b = 0; b < NSIDE; b++) {
            int d0 = rA - b; d0 = d0 < 0 ? -d0 : d0;
            int d1 = rB - b; d1 = d1 < 0 ? -d1 : d1;
            float kd0 = kdtab[d0], kd1 = kdtab[d1];
            float k0  = ktab[d0],  k1  = ktab[d1];
            float4 bv = ld4(sB + b * LDW + c0);
            t1[0].x = fmaf(kd0, bv.x, t1[0].x); t1[0].y = fmaf(kd0, bv.y, t1[0].y);
            t1[0].z = fmaf(kd0, bv.z, t1[0].z); t1[0].w = fmaf(kd0, bv.w, t1[0].w);
            t1[1].x = fmaf(kd1, bv.x, t1[1].x); t1[1].y = fmaf(kd1, bv.y, t1[1].y);
            t1[1].z = fmaf(kd1, bv.z, t1[1].z); t1[1].w = fmaf(kd1, bv.w, t1[1].w);
            t2[0].x = fmaf(k0, bv.x, t2[0].x);  t2[0].y = fmaf(k0, bv.y, t2[0].y);
            t2[0].z = fmaf(k0, bv.z, t2[0].z);  t2[0].w = fmaf(k0, bv.w, t2[0].w);
            t2[1].x = fmaf(k1, bv.x, t2[1].x);  t2[1].y = fmaf(k1, bv.y, t2[1].y);
            t2[1].z = fmaf(k1, bv.z, t2[1].z);  t2[1].w = fmaf(k1, bv.w, t2[1].w);
        }
        __syncthreads();
        st4(&sT[rA * LDW + c0], t1[0]);
        st4(&sT[rB * LDW + c0], t1[1]);
        st4(&sA[rA * LDW + c0], t2[0]);
        st4(&sA[rB * LDW + c0], t2[1]);
        __syncthreads();
    }

    // Pass 2: S1 = T1*K, S2 = T2*KD; cl = sum a .* (S1 + S2)
    float cl = 0.0f;
    {
        float4 s1[2], s2[2];
        s1[0] = s1[1] = s2[0] = s2[1] = make_float4(0.f, 0.f, 0.f, 0.f);
        const float* t1p0 = sT + rA * LDW;
        const float* t1p1 = sT + rB * LDW;
        const float* t2p0 = sA + rA * LDW;
        const float* t2p1 = sA + rB * LDW;
#pragma unroll 8
        for (int b = 0; b < NSIDE; b++) {
            float p0 = t1p0[b], p1 = t1p1[b];
            float q0 = t2p0[b], q1 = t2p1[b];
            float4 kv = ld4(sK + b * LDW + c0);
            int e0 = b - c0;     e0 = e0 < 0 ? -e0 : e0;
            int e1 = b - c0 - 1; e1 = e1 < 0 ? -e1 : e1;
            int e2 = b - c0 - 2; e2 = e2 < 0 ? -e2 : e2;
            int e3 = b - c0 - 3; e3 = e3 < 0 ? -e3 : e3;
            float kd0 = kdtab[e0], kd1 = kdtab[e1], kd2 = kdtab[e2], kd3 = kdtab[e3];
            s1[0].x = fmaf(p0, kv.x, s1[0].x); s1[0].y = fmaf(p0, kv.y, s1[0].y);
            s1[0].z = fmaf(p0, kv.z, s1[0].z); s1[0].w = fmaf(p0, kv.w, s1[0].w);
            s1[1].x = fmaf(p1, kv.x, s1[1].x); s1[1].y = fmaf(p1, kv.y, s1[1].y);
            s1[1].z = fmaf(p1, kv.z, s1[1].z); s1[1].w = fmaf(p1, kv.w, s1[1].w);
            s2[0].x = fmaf(q0, kd0, s2[0].x);  s2[0].y = fmaf(q0, kd1, s2[0].y);
            s2[0].z = fmaf(q0, kd2, s2[0].z);  s2[0].w = fmaf(q0, kd3, s2[0].w);
            s2[1].x = fmaf(q1, kd0, s2[1].x);  s2[1].y = fmaf(q1, kd1, s2[1].y);
            s2[1].z = fmaf(q1, kd2, s2[1].z);  s2[1].w = fmaf(q1, kd3, s2[1].w);
        }
#pragma unroll
        for (int i = 0; i < 2; i++) {
            cl += a4[i].x * (s1[i].x + s2[i].x);
            cl += a4[i].y * (s1[i].y + s2[i].y);
            cl += a4[i].z * (s1[i].z + s2[i].z);
            cl += a4[i].w * (s1[i].w + s2[i].w);
        }
    }

    float c = block_reduce(cl, red);

    // last CTA finalizes the batch mean (counter self-resets: replay-safe)
    if (tid == 0) {
        g_cost[blockIdx.x] = c;
        __threadfence();
        unsigned done = atomicAdd(&g_count, 1u);
        if (done == (unsigned)(nb - 1)) {
            float ssum = 0.0f;
            for (int i = 0; i < nb; i++) ssum += g_cost[i];
            *out = ssum / (float)nb;
            g_count = 0;
        }
    }
}

extern "C" void kernel_launch(void* const* d_in, const int* in_sizes, int n_in,
                              void* d_out, int out_size) {
    const float* y  = (const float*)d_in[0];
    const float* yt = (const float*)d_in[1];
    float* out = (float*)d_out;

    int nb = in_sizes[0] / NPIX;   // 16
    if (nb < 1)    nb = 1;
    if (nb > MAXB) nb = MAXB;

    sinkhorn_kernel<<<nb, NTHREADS>>>(y, yt, out, nb);
}